// round 15
// baseline (speedup 1.0000x reference)
#include <cuda_runtime.h>
#include <cuda_bf16.h>
#include <math.h>

#define N_BINS 15
#define NBLK_MAX 1184
#define PCOLS  48
#define TILE_ROWS 256
#define ROW_BYTES 400                       // C==100 * 4B
#define TILE_BYTES (TILE_ROWS * ROW_BYTES)  // 102400
#define SMEM_DYN   (2 * TILE_BYTES)         // 204800
#define GRID_C100  148

__device__ float g_part[NBLK_MAX][PCOLS];
__device__ unsigned int g_ticket;   // zero-init; last block resets each launch

typedef unsigned long long ull;

__device__ __forceinline__ ull pk2(float lo, float hi) {
    ull r; asm("mov.b64 %0, {%1, %2};" : "=l"(r) : "f"(lo), "f"(hi)); return r;
}
__device__ __forceinline__ void upk2(ull v, float& lo, float& hi) {
    asm("mov.b64 {%0, %1}, %2;" : "=f"(lo), "=f"(hi) : "l"(v));
}
__device__ __forceinline__ ull addx2(ull a, ull b) {
    ull r; asm("add.rn.f32x2 %0, %1, %2;" : "=l"(r) : "l"(a), "l"(b)); return r;
}
__device__ __forceinline__ ull fmasqx2(ull a, ull c) {  // a*a + c
    ull r; asm("fma.rn.f32x2 %0, %1, %2, %3;" : "=l"(r) : "l"(a), "l"(a), "l"(c)); return r;
}
__device__ __forceinline__ void cp16(unsigned int dst, const void* src) {
    asm volatile("cp.async.cg.shared.global [%0], [%1], 16;" :: "r"(dst), "l"(src) : "memory");
}
__device__ __forceinline__ void cp_commit() {
    asm volatile("cp.async.commit_group;" ::: "memory");
}
__device__ __forceinline__ void cp_wait1() {
    asm volatile("cp.async.wait_group 1;" ::: "memory");
}

// C==100: 256-row cp.async double-buffered tiles, thread-per-row from smem,
// 1 block/SM persistent, fused last-block finalize.
__global__ void __launch_bounds__(256) ece_main_c100(
    const float* __restrict__ probs,
    const int* __restrict__ labels,
    float* __restrict__ out,
    int N)
{
    extern __shared__ float4 sm4[];         // 2 x 6400 float4
    __shared__ float s_cnt[N_BINS], s_cf[N_BINS], s_ac[N_BINS], s_bri;

    const int tid = threadIdx.x;
    if (tid < N_BINS) { s_cnt[tid] = 0.f; s_cf[tid] = 0.f; s_ac[tid] = 0.f; }
    if (tid == 0) s_bri = 0.f;

    const int n_tiles = (N + TILE_ROWS - 1) / TILE_ROWS;
    const int stride  = gridDim.x;
    const unsigned int smbase = (unsigned int)__cvta_generic_to_shared(sm4);

    auto issue = [&](int tile, int b) {
        if (tile < n_tiles) {
            int rows  = N - tile * TILE_ROWS;
            if (rows > TILE_ROWS) rows = TILE_ROWS;
            int bytes = rows * ROW_BYTES;
            const char* g = (const char*)probs + (size_t)tile * TILE_BYTES;
            unsigned int d = smbase + (unsigned int)(b * TILE_BYTES);
            #pragma unroll
            for (int i = 0; i < 25; i++) {
                int off = tid * 16 + i * 4096;     // 256 thr * 16B = 4096
                if (off < bytes) cp16(d + off, g + off);
            }
        }
        cp_commit();
    };

    // per-thread bin run-length accumulator (bin 0 dominates)
    int   cur_bin = -1;
    float f_cnt = 0.f, f_cf = 0.f, f_ac = 0.f, briacc = 0.f;
    auto flush = [&]() {
        if (cur_bin >= 0) {
            atomicAdd(&s_cnt[cur_bin], f_cnt);
            atomicAdd(&s_cf[cur_bin],  f_cf);
            atomicAdd(&s_ac[cur_bin],  f_ac);
        }
    };

    issue(blockIdx.x, 0);
    int buf = 0;
    for (int t = blockIdx.x; t < n_tiles; t += stride) {
        // prefetch labels for THIS tile (independent LDG, overlaps the wait)
        int row = t * TILE_ROWS + tid;
        int lab = (row < N) ? labels[row] : 0;

        issue(t + stride, buf ^ 1);        // next tile into other buffer
        cp_wait1();                        // tile t complete
        __syncthreads();

        if (row < N) {
            const float4* rp = sm4 + buf * (TILE_BYTES / 16) + tid * 25;
            ull sa = 0, sb = 0, qa = 0, qb = 0;
            float m = 0.f;
            #pragma unroll
            for (int i = 0; i < 25; i++) {
                float4 v = rp[i];
                ull v01 = pk2(v.x, v.y), v23 = pk2(v.z, v.w);
                sa = addx2(sa, v01);
                sb = addx2(sb, v23);
                qa = fmasqx2(v01, qa);
                qb = fmasqx2(v23, qb);
                m = fmaxf(m, fmaxf(fmaxf(v.x, v.y), fmaxf(v.z, v.w)));
            }
            float slo, shi, qlo, qhi, s, sq;
            upk2(addx2(sa, sb), slo, shi); s  = slo + shi;
            upk2(addx2(qa, qb), qlo, qhi); sq = qlo + qhi;

            int labc = lab < 0 ? 0 : (lab > 99 ? 99 : lab);
            float pl = ((const float*)rp)[labc];

            float inv  = __fdividef(1.f, s);
            float conf = m * inv;
            float bri  = sq * inv * inv - 2.f * pl * inv + 1.f;
            float hit  = (pl == m) ? 1.f : 0.f;
            int bin = __float2int_ru(conf * (float)N_BINS) - 1;
            bin = bin < 0 ? 0 : (bin > N_BINS - 1 ? N_BINS - 1 : bin);

            if (bin != cur_bin) {
                flush();
                cur_bin = bin; f_cnt = 1.f; f_cf = conf; f_ac = hit;
            } else {
                f_cnt += 1.f; f_cf += conf; f_ac += hit;
            }
            briacc += bri;
        }
        __syncthreads();                   // compute done before buffer reuse
        buf ^= 1;
    }

    flush();
    if (briacc != 0.f) atomicAdd(&s_bri, briacc);
    __syncthreads();

    if (tid < N_BINS) {
        g_part[blockIdx.x][tid]              = s_cnt[tid];
        g_part[blockIdx.x][tid + N_BINS]     = s_cf[tid];
        g_part[blockIdx.x][tid + 2 * N_BINS] = s_ac[tid];
    }
    if (tid == 0) g_part[blockIdx.x][45] = s_bri;

    // fused finalize
    __shared__ bool is_last;
    __threadfence();
    if (tid == 0) {
        unsigned int tk = atomicAdd(&g_ticket, 1u);
        is_last = (tk == gridDim.x - 1);
    }
    __syncthreads();

    if (is_last) {
        if (tid == 0) g_ticket = 0;
        __shared__ double col[46];
        const int c     = tid & 63;
        const int chunk = tid >> 6;        // 0..3
        if (tid < 46) col[tid] = 0.0;
        __syncthreads();
        if (c < 46) {
            double acc = 0.0;
            for (int b = chunk; b < (int)gridDim.x; b += 4)
                acc += (double)g_part[b][c];
            atomicAdd(&col[c], acc);
        }
        __syncthreads();
        if (tid == 0) {
            double ece = 0.0, mx = 0.0;
            double invN = 1.0 / (double)N;
            #pragma unroll
            for (int b = 0; b < N_BINS; b++) {
                double cc = col[b];
                if (cc > 0.0) {
                    double gap = fabs(col[b + N_BINS] / cc - col[b + 2 * N_BINS] / cc);
                    ece += gap * cc * invN;
                    if (gap > mx) mx = gap;
                }
            }
            out[0] = (float)ece;
            out[1] = (float)mx;
            out[2] = (float)(col[45] * invN);
        }
    }
}

// Generic fallback: warp-per-row, fused finalize.
__global__ void ece_main_generic(const float* __restrict__ probs,
                                 const int* __restrict__ labels,
                                 float* __restrict__ out,
                                 int N, int C) {
    __shared__ float s_cnt[N_BINS], s_cf[N_BINS], s_ac[N_BINS], s_bri;
    if (threadIdx.x < N_BINS) {
        s_cnt[threadIdx.x] = 0.f; s_cf[threadIdx.x] = 0.f; s_ac[threadIdx.x] = 0.f;
    }
    if (threadIdx.x == 0) s_bri = 0.f;
    __syncthreads();

    const int lane  = threadIdx.x & 31;
    const int warp  = (blockIdx.x * blockDim.x + threadIdx.x) >> 5;
    const int nwarp = (gridDim.x * blockDim.x) >> 5;

    float acc_count = 0.f, acc_conf = 0.f, acc_acc = 0.f, acc_bri = 0.f;

    for (int row = warp; row < N; row += nwarp) {
        const float* rp = probs + (size_t)row * C;
        float s = 0.f, sq = 0.f, m = -1.f;
        for (int c = lane; c < C; c += 32) {
            float x = rp[c];
            s += x; sq += x * x;
            m = fmaxf(m, x);
        }
        #pragma unroll
        for (int off = 16; off >= 1; off >>= 1) {
            s  += __shfl_xor_sync(0xffffffffu, s,  off);
            sq += __shfl_xor_sync(0xffffffffu, sq, off);
            m = fmaxf(m, __shfl_xor_sync(0xffffffffu, m, off));
        }
        int lab = labels[row];
        int labc = lab < 0 ? 0 : (lab >= C ? C - 1 : lab);
        float pl = rp[labc];
        float inv  = __fdividef(1.f, s);
        float conf = m * inv;
        float bri  = sq * inv * inv - 2.f * pl * inv + 1.f;
        float hit  = (pl == m) ? 1.f : 0.f;
        int bin = __float2int_ru(conf * (float)N_BINS) - 1;
        bin = bin < 0 ? 0 : (bin > N_BINS - 1 ? N_BINS - 1 : bin);
        if (lane == bin) { acc_count += 1.f; acc_conf += conf; acc_acc += hit; }
        if (lane == 0) acc_bri += bri;
    }

    if (lane < N_BINS && acc_count > 0.f) {
        atomicAdd(&s_cnt[lane], acc_count);
        atomicAdd(&s_cf[lane],  acc_conf);
        atomicAdd(&s_ac[lane],  acc_acc);
    }
    if (lane == 0 && acc_bri != 0.f) atomicAdd(&s_bri, acc_bri);
    __syncthreads();

    {
        int t = threadIdx.x;
        if (t < N_BINS) {
            g_part[blockIdx.x][t]              = s_cnt[t];
            g_part[blockIdx.x][t + N_BINS]     = s_cf[t];
            g_part[blockIdx.x][t + 2 * N_BINS] = s_ac[t];
        }
        if (t == 0) g_part[blockIdx.x][45] = s_bri;
    }

    __shared__ bool is_last;
    __threadfence();
    if (threadIdx.x == 0) {
        unsigned int tk = atomicAdd(&g_ticket, 1u);
        is_last = (tk == gridDim.x - 1);
    }
    __syncthreads();

    if (is_last) {
        if (threadIdx.x == 0) g_ticket = 0;
        __shared__ double col[46];
        const int c     = threadIdx.x & 63;
        const int chunk = threadIdx.x >> 6;
        if (threadIdx.x < 46) col[threadIdx.x] = 0.0;
        __syncthreads();
        if (c < 46) {
            double acc = 0.0;
            for (int b = chunk; b < (int)gridDim.x; b += 4)
                acc += (double)g_part[b][c];
            atomicAdd(&col[c], acc);
        }
        __syncthreads();
        if (threadIdx.x == 0) {
            double ece = 0.0, mx = 0.0;
            double invN = 1.0 / (double)N;
            #pragma unroll
            for (int b = 0; b < N_BINS; b++) {
                double cc = col[b];
                if (cc > 0.0) {
                    double gap = fabs(col[b + N_BINS] / cc - col[b + 2 * N_BINS] / cc);
                    ece += gap * cc * invN;
                    if (gap > mx) mx = gap;
                }
            }
            out[0] = (float)ece;
            out[1] = (float)mx;
            out[2] = (float)(col[45] * invN);
        }
    }
}

extern "C" void kernel_launch(void* const* d_in, const int* in_sizes, int n_in,
                              void* d_out, int out_size) {
    int i_probs = 0, i_labels = 1;
    if (n_in >= 2 && in_sizes[1] > in_sizes[0]) { i_probs = 1; i_labels = 0; }
    const float* probs  = (const float*)d_in[i_probs];
    const int*   labels = (const int*)d_in[i_labels];
    int N = in_sizes[i_labels];
    int C = in_sizes[i_probs] / N;
    float* out = (float*)d_out;

    if (C == 100) {
        cudaFuncSetAttribute(ece_main_c100,
                             cudaFuncAttributeMaxDynamicSharedMemorySize, SMEM_DYN);
        ece_main_c100<<<GRID_C100, 256, SMEM_DYN>>>(probs, labels, out, N);
    } else {
        ece_main_generic<<<1184, 256>>>(probs, labels, out, N, C);
    }
}

// round 16
// speedup vs baseline: 1.3817x; 1.3817x over previous
#include <cuda_runtime.h>
#include <cuda_bf16.h>
#include <math.h>

#define N_BINS 15
#define NBLK_MAX 1184
#define PCOLS  48
#define GRID_C100 592

__device__ float g_part[NBLK_MAX][PCOLS];
__device__ unsigned int g_ticket;   // zero-init; last block resets each launch

typedef unsigned long long ull;

__device__ __forceinline__ ull pk2(float lo, float hi) {
    ull r; asm("mov.b64 %0, {%1, %2};" : "=l"(r) : "f"(lo), "f"(hi)); return r;
}
__device__ __forceinline__ void upk2(ull v, float& lo, float& hi) {
    asm("mov.b64 {%0, %1}, %2;" : "=f"(lo), "=f"(hi) : "l"(v));
}
__device__ __forceinline__ ull addx2(ull a, ull b) {
    ull r; asm("add.rn.f32x2 %0, %1, %2;" : "=l"(r) : "l"(a), "l"(b)); return r;
}
__device__ __forceinline__ ull fmasqx2(ull a, ull c) {  // a*a + c
    ull r; asm("fma.rn.f32x2 %0, %1, %2, %3;" : "=l"(r) : "l"(a), "l"(a), "l"(c)); return r;
}

// C==100: 4 lanes/row, 8 rows per warp-iteration, 7 independent LDG.128/lane,
// run-length bin accumulation, fused last-block finalize.
__global__ void __launch_bounds__(256, 4) ece_main_c100(
    const float4* __restrict__ probs4,
    const int* __restrict__ labels,
    float* __restrict__ out,
    int N)
{
    __shared__ float s_cnt[N_BINS], s_cf[N_BINS], s_ac[N_BINS], s_bri;
    const int tid = threadIdx.x;
    if (tid < N_BINS) { s_cnt[tid] = 0.f; s_cf[tid] = 0.f; s_ac[tid] = 0.f; }
    if (tid == 0) s_bri = 0.f;
    __syncthreads();

    const int lane = tid & 31;
    const int k    = lane & 3;           // lane within 4-lane row-group
    const int g    = lane >> 2;          // row-group 0..7
    const int warp = (blockIdx.x * blockDim.x + tid) >> 5;
    const int nwarp = (gridDim.x * blockDim.x) >> 5;
    const int step  = nwarp * 8;

    // run-length bin accumulator (only k==0 lanes use it)
    int   cur_bin = -1;
    float f_cnt = 0.f, f_cf = 0.f, f_ac = 0.f, briacc = 0.f;

    for (int r8 = warp * 8; r8 < N; r8 += step) {
        int row   = r8 + g;
        bool valid = (row < N);
        int rowc  = valid ? row : 0;

        // labels first (independent of probs loads)
        int lab = labels[rowc];

        const float4* rp = probs4 + (size_t)rowc * 25;
        // 7 independent loads: slots k, k+4, ..., k+20, and slot 24 on k==0
        float4 c0 = rp[k];
        float4 c1 = rp[k + 4];
        float4 c2 = rp[k + 8];
        float4 c3 = rp[k + 12];
        float4 c4 = rp[k + 16];
        float4 c5 = rp[k + 20];
        float4 c6 = (k == 0) ? rp[24] : make_float4(0.f, 0.f, 0.f, 0.f);

        // packed sum / sumsq, scalar max
        ull v01, v23, sa, sb, qa, qb;
        v01 = pk2(c0.x, c0.y); v23 = pk2(c0.z, c0.w);
        sa = addx2(v01, v23);  qa = fmasqx2(v01, fmasqx2(v23, 0ull));
        float m = fmaxf(fmaxf(c0.x, c0.y), fmaxf(c0.z, c0.w));

        v01 = pk2(c1.x, c1.y); v23 = pk2(c1.z, c1.w);
        sb = addx2(v01, v23);  qb = fmasqx2(v01, fmasqx2(v23, 0ull));
        m = fmaxf(m, fmaxf(fmaxf(c1.x, c1.y), fmaxf(c1.z, c1.w)));

        v01 = pk2(c2.x, c2.y); v23 = pk2(c2.z, c2.w);
        sa = addx2(sa, addx2(v01, v23));  qa = fmasqx2(v01, fmasqx2(v23, qa));
        m = fmaxf(m, fmaxf(fmaxf(c2.x, c2.y), fmaxf(c2.z, c2.w)));

        v01 = pk2(c3.x, c3.y); v23 = pk2(c3.z, c3.w);
        sb = addx2(sb, addx2(v01, v23));  qb = fmasqx2(v01, fmasqx2(v23, qb));
        m = fmaxf(m, fmaxf(fmaxf(c3.x, c3.y), fmaxf(c3.z, c3.w)));

        v01 = pk2(c4.x, c4.y); v23 = pk2(c4.z, c4.w);
        sa = addx2(sa, addx2(v01, v23));  qa = fmasqx2(v01, fmasqx2(v23, qa));
        m = fmaxf(m, fmaxf(fmaxf(c4.x, c4.y), fmaxf(c4.z, c4.w)));

        v01 = pk2(c5.x, c5.y); v23 = pk2(c5.z, c5.w);
        sb = addx2(sb, addx2(v01, v23));  qb = fmasqx2(v01, fmasqx2(v23, qb));
        m = fmaxf(m, fmaxf(fmaxf(c5.x, c5.y), fmaxf(c5.z, c5.w)));

        v01 = pk2(c6.x, c6.y); v23 = pk2(c6.z, c6.w);
        sa = addx2(sa, addx2(v01, v23));  qa = fmasqx2(v01, fmasqx2(v23, qa));
        m = fmaxf(m, fmaxf(fmaxf(c6.x, c6.y), fmaxf(c6.z, c6.w)));

        ull s2 = addx2(sa, sb);
        ull q2 = addx2(qa, qb);

        // 2-stage butterfly within the 4-lane group
        #pragma unroll
        for (int off = 2; off >= 1; off >>= 1) {
            s2 = addx2(s2, __shfl_xor_sync(0xffffffffu, s2, off));
            q2 = addx2(q2, __shfl_xor_sync(0xffffffffu, q2, off));
            m  = fmaxf(m, __shfl_xor_sync(0xffffffffu, m, off));
        }
        float slo, shi, qlo, qhi;
        upk2(s2, slo, shi); float s  = slo + shi;
        upk2(q2, qlo, qhi); float sq = qlo + qhi;

        // p[label]: slot = labc>>2 owned by lane (slot&3), register (slot>>2)
        int labc = lab < 0 ? 0 : (lab > 99 ? 99 : lab);
        int slot = labc >> 2;
        int ridx = slot >> 2;            // 0..6 (slot 24 -> 6)
        int owner = slot & 3;            // slot 24 -> 0
        int comp = labc & 3;
        float4 vsel = (ridx == 0) ? c0 : (ridx == 1) ? c1 : (ridx == 2) ? c2 :
                      (ridx == 3) ? c3 : (ridx == 4) ? c4 : (ridx == 5) ? c5 : c6;
        float cand = (comp == 0) ? vsel.x : (comp == 1) ? vsel.y :
                     (comp == 2) ? vsel.z : vsel.w;
        float pl = __shfl_sync(0xffffffffu, cand, (lane & ~3) | owner);

        if (k == 0 && valid) {
            float inv  = __fdividef(1.f, s);
            float conf = m * inv;
            float bri  = sq * inv * inv - 2.f * pl * inv + 1.f;
            float hit  = (pl == m) ? 1.f : 0.f;
            int bin = __float2int_ru(conf * (float)N_BINS) - 1;
            bin = bin < 0 ? 0 : (bin > N_BINS - 1 ? N_BINS - 1 : bin);

            if (bin != cur_bin) {
                if (cur_bin >= 0) {
                    atomicAdd(&s_cnt[cur_bin], f_cnt);
                    atomicAdd(&s_cf[cur_bin],  f_cf);
                    atomicAdd(&s_ac[cur_bin],  f_ac);
                }
                cur_bin = bin; f_cnt = 1.f; f_cf = conf; f_ac = hit;
            } else {
                f_cnt += 1.f; f_cf += conf; f_ac += hit;
            }
            briacc += bri;
        }
    }

    if (cur_bin >= 0) {
        atomicAdd(&s_cnt[cur_bin], f_cnt);
        atomicAdd(&s_cf[cur_bin],  f_cf);
        atomicAdd(&s_ac[cur_bin],  f_ac);
    }
    if (briacc != 0.f) atomicAdd(&s_bri, briacc);
    __syncthreads();

    if (tid < N_BINS) {
        g_part[blockIdx.x][tid]              = s_cnt[tid];
        g_part[blockIdx.x][tid + N_BINS]     = s_cf[tid];
        g_part[blockIdx.x][tid + 2 * N_BINS] = s_ac[tid];
    }
    if (tid == 0) g_part[blockIdx.x][45] = s_bri;

    // fused finalize: last block reduces all partials (L2-hot)
    __shared__ bool is_last;
    __threadfence();
    if (tid == 0) {
        unsigned int tk = atomicAdd(&g_ticket, 1u);
        is_last = (tk == gridDim.x - 1);
    }
    __syncthreads();

    if (is_last) {
        if (tid == 0) g_ticket = 0;
        __shared__ double col[46];
        const int c     = tid & 63;
        const int chunk = tid >> 6;      // 0..3
        if (tid < 46) col[tid] = 0.0;
        __syncthreads();
        if (c < 46) {
            double acc = 0.0;
            for (int b = chunk; b < (int)gridDim.x; b += 4)
                acc += (double)g_part[b][c];
            atomicAdd(&col[c], acc);
        }
        __syncthreads();
        if (tid == 0) {
            double ece = 0.0, mx = 0.0;
            double invN = 1.0 / (double)N;
            #pragma unroll
            for (int b = 0; b < N_BINS; b++) {
                double cc = col[b];
                if (cc > 0.0) {
                    double gap = fabs(col[b + N_BINS] / cc - col[b + 2 * N_BINS] / cc);
                    ece += gap * cc * invN;
                    if (gap > mx) mx = gap;
                }
            }
            out[0] = (float)ece;
            out[1] = (float)mx;
            out[2] = (float)(col[45] * invN);
        }
    }
}

// Generic fallback: warp-per-row, fused finalize.
__global__ void ece_main_generic(const float* __restrict__ probs,
                                 const int* __restrict__ labels,
                                 float* __restrict__ out,
                                 int N, int C) {
    __shared__ float s_cnt[N_BINS], s_cf[N_BINS], s_ac[N_BINS], s_bri;
    if (threadIdx.x < N_BINS) {
        s_cnt[threadIdx.x] = 0.f; s_cf[threadIdx.x] = 0.f; s_ac[threadIdx.x] = 0.f;
    }
    if (threadIdx.x == 0) s_bri = 0.f;
    __syncthreads();

    const int lane  = threadIdx.x & 31;
    const int warp  = (blockIdx.x * blockDim.x + threadIdx.x) >> 5;
    const int nwarp = (gridDim.x * blockDim.x) >> 5;

    float acc_count = 0.f, acc_conf = 0.f, acc_acc = 0.f, acc_bri = 0.f;

    for (int row = warp; row < N; row += nwarp) {
        const float* rp = probs + (size_t)row * C;
        float s = 0.f, sq = 0.f, m = -1.f;
        for (int c = lane; c < C; c += 32) {
            float x = rp[c];
            s += x; sq += x * x;
            m = fmaxf(m, x);
        }
        #pragma unroll
        for (int off = 16; off >= 1; off >>= 1) {
            s  += __shfl_xor_sync(0xffffffffu, s,  off);
            sq += __shfl_xor_sync(0xffffffffu, sq, off);
            m = fmaxf(m, __shfl_xor_sync(0xffffffffu, m, off));
        }
        int lab = labels[row];
        int labc = lab < 0 ? 0 : (lab >= C ? C - 1 : lab);
        float pl = rp[labc];
        float inv  = __fdividef(1.f, s);
        float conf = m * inv;
        float bri  = sq * inv * inv - 2.f * pl * inv + 1.f;
        float hit  = (pl == m) ? 1.f : 0.f;
        int bin = __float2int_ru(conf * (float)N_BINS) - 1;
        bin = bin < 0 ? 0 : (bin > N_BINS - 1 ? N_BINS - 1 : bin);
        if (lane == bin) { acc_count += 1.f; acc_conf += conf; acc_acc += hit; }
        if (lane == 0) acc_bri += bri;
    }

    if (lane < N_BINS && acc_count > 0.f) {
        atomicAdd(&s_cnt[lane], acc_count);
        atomicAdd(&s_cf[lane],  acc_conf);
        atomicAdd(&s_ac[lane],  acc_acc);
    }
    if (lane == 0 && acc_bri != 0.f) atomicAdd(&s_bri, acc_bri);
    __syncthreads();

    {
        int t = threadIdx.x;
        if (t < N_BINS) {
            g_part[blockIdx.x][t]              = s_cnt[t];
            g_part[blockIdx.x][t + N_BINS]     = s_cf[t];
            g_part[blockIdx.x][t + 2 * N_BINS] = s_ac[t];
        }
        if (t == 0) g_part[blockIdx.x][45] = s_bri;
    }

    __shared__ bool is_last;
    __threadfence();
    if (threadIdx.x == 0) {
        unsigned int tk = atomicAdd(&g_ticket, 1u);
        is_last = (tk == gridDim.x - 1);
    }
    __syncthreads();

    if (is_last) {
        if (threadIdx.x == 0) g_ticket = 0;
        __shared__ double col[46];
        const int c     = threadIdx.x & 63;
        const int chunk = threadIdx.x >> 6;
        if (threadIdx.x < 46) col[threadIdx.x] = 0.0;
        __syncthreads();
        if (c < 46) {
            double acc = 0.0;
            for (int b = chunk; b < (int)gridDim.x; b += 4)
                acc += (double)g_part[b][c];
            atomicAdd(&col[c], acc);
        }
        __syncthreads();
        if (threadIdx.x == 0) {
            double ece = 0.0, mx = 0.0;
            double invN = 1.0 / (double)N;
            #pragma unroll
            for (int b = 0; b < N_BINS; b++) {
                double cc = col[b];
                if (cc > 0.0) {
                    double gap = fabs(col[b + N_BINS] / cc - col[b + 2 * N_BINS] / cc);
                    ece += gap * cc * invN;
                    if (gap > mx) mx = gap;
                }
            }
            out[0] = (float)ece;
            out[1] = (float)mx;
            out[2] = (float)(col[45] * invN);
        }
    }
}

extern "C" void kernel_launch(void* const* d_in, const int* in_sizes, int n_in,
                              void* d_out, int out_size) {
    int i_probs = 0, i_labels = 1;
    if (n_in >= 2 && in_sizes[1] > in_sizes[0]) { i_probs = 1; i_labels = 0; }
    const float* probs  = (const float*)d_in[i_probs];
    const int*   labels = (const int*)d_in[i_labels];
    int N = in_sizes[i_labels];
    int C = in_sizes[i_probs] / N;
    float* out = (float*)d_out;

    if (C == 100) {
        ece_main_c100<<<GRID_C100, 256>>>((const float4*)probs, labels, out, N);
    } else {
        ece_main_generic<<<1184, 256>>>(probs, labels, out, N, C);
    }
}